// round 1
// baseline (speedup 1.0000x reference)
#include <cuda_runtime.h>

// ParallelBellowsLayers: per-channel 1->16->1 MLP with ReLU, C=40000 channels,
// B=128, E=16.  out[b, c] = relu( sum_e relu(x[b,c]*w1[c,e]+b1[c,e]) * w2[c,e] + b2[c] )
// Output tensor (B, 2, 20000) is memory-layout-identical to (B, C) row-major,
// i.e. elementwise in x's own layout.
//
// Key transform: when b1[c,:] == 0 (true for this dataset),
//   sum_e relu(x*w1e)*w2e  ==  x * s_pos(c)   if x > 0
//                          ==  x * s_neg(c)   if x < 0
// with s_pos = sum_{w1e>0} w1e*w2e, s_neg = sum_{w1e<0} w1e*w2e.
// Precompute (s_pos, s_neg) per channel once per launch (cheap: 7.7 MB read),
// then the main pass is a pure streaming elementwise op (~41 MB traffic).
// Channels with any nonzero b1 get a NaN sentinel and take an exact
// per-element fallback path (never taken on this dataset).

#define NGENES 20000
#define NTECH  2
#define CC     (NGENES * NTECH)   // 40000
#define BB     128
#define EE     16

// scratch: per-channel (s_pos, s_neg); NaN in .x => fallback channel
__device__ float2 g_scale[CC];

__global__ void __launch_bounds__(256)
precompute_kernel(const float* __restrict__ w1,
                  const float* __restrict__ b1,
                  const float* __restrict__ w2)
{
    int c = blockIdx.x * 256 + threadIdx.x;
    if (c >= CC) return;

    const float4* w1v = reinterpret_cast<const float4*>(w1 + (size_t)c * EE);
    const float4* b1v = reinterpret_cast<const float4*>(b1 + (size_t)c * EE);
    const float4* w2v = reinterpret_cast<const float4*>(w2 + (size_t)c * EE);

    float sp = 0.f, sn = 0.f;
    bool b1zero = true;

#pragma unroll
    for (int i = 0; i < 4; ++i) {
        float4 a = w1v[i];
        float4 z = b1v[i];
        float4 w = w2v[i];
        b1zero = b1zero && (z.x == 0.f) && (z.y == 0.f) && (z.z == 0.f) && (z.w == 0.f);

        float p;
        p = a.x * w.x; sp += (a.x > 0.f) ? p : 0.f; sn += (a.x < 0.f) ? p : 0.f;
        p = a.y * w.y; sp += (a.y > 0.f) ? p : 0.f; sn += (a.y < 0.f) ? p : 0.f;
        p = a.z * w.z; sp += (a.z > 0.f) ? p : 0.f; sn += (a.z < 0.f) ? p : 0.f;
        p = a.w * w.w; sp += (a.w > 0.f) ? p : 0.f; sn += (a.w < 0.f) ? p : 0.f;
    }

    if (!b1zero) sp = __int_as_float(0x7fc00000);  // NaN sentinel -> exact fallback
    g_scale[c] = make_float2(sp, sn);
}

// Exact per-element path for channels with nonzero b1. Never taken on this
// dataset; __noinline__ keeps it from inflating fast-path register pressure.
__device__ __noinline__ float bellows_exact(float xv, int c,
                                            const float* __restrict__ w1,
                                            const float* __restrict__ b1,
                                            const float* __restrict__ w2,
                                            float bias)
{
    float acc = 0.f;
    const float* w1r = w1 + (size_t)c * EE;
    const float* b1r = b1 + (size_t)c * EE;
    const float* w2r = w2 + (size_t)c * EE;
#pragma unroll 4
    for (int e = 0; e < EE; ++e) {
        float h = fmaxf(fmaf(xv, w1r[e], b1r[e]), 0.f);
        acc = fmaf(h, w2r[e], acc);
    }
    return fmaxf(acc + bias, 0.f);
}

__device__ __forceinline__ float bellows_fast(float xv, float sp, float sn, float bias)
{
    float s = (xv > 0.f) ? sp : sn;
    return fmaxf(fmaf(xv, s, bias), 0.f);
}

__global__ void __launch_bounds__(256)
apply_kernel(const float* __restrict__ x,
             const float* __restrict__ w1,
             const float* __restrict__ b1,
             const float* __restrict__ w2,
             const float* __restrict__ b2,
             float* __restrict__ out)
{
    int j = blockIdx.x * 256 + threadIdx.x;   // float4 index within a row
    if (j >= CC / 4) return;
    int b = blockIdx.y;
    int c = j * 4;
    size_t base = (size_t)b * CC + c;

    float4 xv = *reinterpret_cast<const float4*>(x + base);
    float4 bv = *reinterpret_cast<const float4*>(b2 + c);

    // g_scale viewed as float4: sA = {sp0, sn0, sp1, sn1}, sB = {sp2, sn2, sp3, sn3}
    const float4* sc = reinterpret_cast<const float4*>(g_scale);
    float4 sA = sc[2 * j];
    float4 sB = sc[2 * j + 1];

    float4 o;
    bool any_nan = (sA.x != sA.x) || (sA.z != sA.z) || (sB.x != sB.x) || (sB.z != sB.z);
    if (!any_nan) {
        o.x = bellows_fast(xv.x, sA.x, sA.y, bv.x);
        o.y = bellows_fast(xv.y, sA.z, sA.w, bv.y);
        o.z = bellows_fast(xv.z, sB.x, sB.y, bv.z);
        o.w = bellows_fast(xv.w, sB.z, sB.w, bv.w);
    } else {
        o.x = (sA.x != sA.x) ? bellows_exact(xv.x, c + 0, w1, b1, w2, bv.x)
                             : bellows_fast(xv.x, sA.x, sA.y, bv.x);
        o.y = (sA.z != sA.z) ? bellows_exact(xv.y, c + 1, w1, b1, w2, bv.y)
                             : bellows_fast(xv.y, sA.z, sA.w, bv.y);
        o.z = (sB.x != sB.x) ? bellows_exact(xv.z, c + 2, w1, b1, w2, bv.z)
                             : bellows_fast(xv.z, sB.x, sB.y, bv.z);
        o.w = (sB.z != sB.z) ? bellows_exact(xv.w, c + 3, w1, b1, w2, bv.w)
                             : bellows_fast(xv.w, sB.z, sB.w, bv.w);
    }

    *reinterpret_cast<float4*>(out + base) = o;
}

extern "C" void kernel_launch(void* const* d_in, const int* in_sizes, int n_in,
                              void* d_out, int out_size)
{
    const float* x  = (const float*)d_in[0];   // (128, 40000)
    const float* w1 = (const float*)d_in[1];   // (40000, 16)
    const float* b1 = (const float*)d_in[2];   // (40000, 16)
    const float* w2 = (const float*)d_in[3];   // (40000, 16)
    const float* b2 = (const float*)d_in[4];   // (40000,)
    float* out = (float*)d_out;                // (128, 2, 20000) == (128, 40000)

    precompute_kernel<<<(CC + 255) / 256, 256>>>(w1, b1, w2);

    dim3 grid((CC / 4 + 255) / 256, BB);       // (40, 128)
    apply_kernel<<<grid, 256>>>(x, w1, b1, w2, b2, out);
}